// round 3
// baseline (speedup 1.0000x reference)
#include <cuda_runtime.h>
#include <cuda_bf16.h>

#define Bv 64
#define Tv 100
#define Av 8732
typedef unsigned long long ull;

// per-(b,t) packed winner: (q_bits << 32) | (0xFFFFFFFF - anchor)
__device__ ull  g_key[Bv * Tv];
// per-(b,a) best-over-t: {q_bits, ct}
__device__ int2 g_best[Bv * Av];

// exact max(x, 0) on the fma pipe: 0.5*(x+|x|)
__device__ __forceinline__ float clamp0(float x) {
    return __fmul_rn(__fadd_rn(x, fabsf(x)), 0.5f);
}
// safe reject-filter slope for quotient q: never rejects q' >= q
__device__ __forceinline__ float slope_of(float q) {
    return __fmul_rn(__fdividef(q, __fadd_rn(1.f, q)), 0.99999f);
}

// K0: zero g_key (6400 ull).
__global__ __launch_bounds__(256) void k_fill() {
    int i = blockIdx.x * 256 + threadIdx.x;
    if (i < Bv * Tv) g_key[i] = 0ull;
}

// K1 (fused): one pass over all (b,t,a) IoUs.
// Grid: (ceil(A/256), B), block 256. Thread = one anchor; loop over t.
// Produces: g_best[b,a] = per-anchor argmax over t; g_key[b,t] = per-t argmax
// over anchors (exact quotient key, tie -> lowest anchor index).
__global__ __launch_bounds__(256) void k_fused(
        const float* __restrict__ targets,
        const float* __restrict__ anchors) {
    __shared__ float4 sbox[Tv];
    __shared__ float  sarea[Tv];
    __shared__ int    sslope[Tv];   // float bits, monotone via atomicMax
    __shared__ ull    skey[Tv];

    const int b   = blockIdx.y;
    const int tid = threadIdx.x;
    if (tid < Tv) {
        const float* tp = targets + ((size_t)b * Tv + tid) * 5;
        float x1 = tp[0], y1 = tp[1], x2 = tp[2], y2 = tp[3];
        sbox[tid]   = make_float4(x1, y1, x2, y2);
        sarea[tid]  = __fmul_rn(__fsub_rn(x2, x1), __fsub_rn(y2, y1));
        sslope[tid] = 0;
        skey[tid]   = 0ull;
    }
    __syncthreads();

    const int a0 = blockIdx.x * 256 + tid;
    const int a  = min(a0, Av - 1);          // clamped lanes duplicate a=Av-1 (harmless)

    float4 an = __ldg((const float4*)anchors + a);
    float hw  = __fmul_rn(an.z, 0.5f), hh = __fmul_rn(an.w, 0.5f);
    float ax1 = __fsub_rn(an.x, hw),  ay1 = __fsub_rn(an.y, hh);
    float ax2 = __fadd_rn(an.x, hw),  ay2 = __fadd_rn(an.y, hh);
    float aa  = __fmul_rn(__fsub_rn(ax2, ax1), __fsub_rn(ay2, ay1));

    float q = 0.f, s = 0.f; int ct = 0;
#pragma unroll 5
    for (int t = 0; t < Tv; t++) {
        float4 bx  = sbox[t];
        float area = sarea[t];
        float slp  = __int_as_float(sslope[t]);  // stale reads only loosen filter
        float dx = clamp0(__fsub_rn(fminf(bx.z, ax2), fmaxf(bx.x, ax1)));
        float dy = clamp0(__fsub_rn(fminf(bx.w, ay2), fmaxf(bx.y, ay1)));
        float inter = __fmul_rn(dx, dy);
        float sab   = __fadd_rn(area, aa);
        float m     = fminf(s, slp);
        if (inter > __fmul_rn(m, sab)) {                     // rare path
            float qc = __fdiv_rn(inter, __fsub_rn(sab, inter));  // exact IoU
            if (qc > q) { q = qc; ct = t; s = slope_of(qc); }    // first-t wins
            if (inter > __fmul_rn(slp, sab)) {               // per-t candidate
                ull key = ((ull)__float_as_uint(qc) << 32)
                        | (unsigned)(0xFFFFFFFFu - (unsigned)a);
                atomicMax(&skey[t], key);                    // tie -> lowest a
                atomicMax(&sslope[t], __float_as_int(slope_of(qc)));
            }
        }
    }

    if (a0 < Av)
        g_best[(size_t)b * Av + a0] = make_int2(__float_as_int(q), ct);

    __syncthreads();
    if (tid < Tv && skey[tid])
        atomicMax(&g_key[b * Tv + tid], skey[tid]);
}

// K2 (epilogue): per (b,a) resolve forced match, encode loc, compute conf.
// Grid: (ceil(A/256), B), block 256.
__global__ __launch_bounds__(256) void k_epi(
        const float* __restrict__ targets,
        const float* __restrict__ anchors,
        float* __restrict__ out) {
    __shared__ float4 sbox[Tv];
    __shared__ float  slab[Tv];
    __shared__ int    sforced[256];

    const int b   = blockIdx.y;
    const int tid = threadIdx.x;
    const unsigned a0blk = blockIdx.x * 256u;

    sforced[tid] = -1;
    if (tid < Tv) {
        const float* tp = targets + ((size_t)b * Tv + tid) * 5;
        sbox[tid] = make_float4(tp[0], tp[1], tp[2], tp[3]);
        slab[tid] = tp[4];
    }
    __syncthreads();
    if (tid < Tv) {
        ull key = g_key[b * Tv + tid];
        unsigned aw = key ? (0xFFFFFFFFu - (unsigned)key) : 0u;
        unsigned rel = aw - a0blk;
        if (rel < 256u) atomicMax(&sforced[rel], tid);   // max t = last write wins
    }
    __syncthreads();

    const unsigned a = a0blk + tid;
    if (a >= Av) return;

    float4 an = __ldg((const float4*)anchors + a);
    int2 bv  = g_best[(size_t)b * Av + a];
    float q  = __int_as_float(bv.x);
    int   ct = bv.y;
    int forced = sforced[tid];

    int gt, conf;
    if (forced >= 0) { gt = forced; conf = (int)slab[gt] + 1; }   // overlap := 1.0
    else             { gt = ct;     conf = (q < 0.5f) ? 0 : ((int)slab[gt] + 1); }

    float4 m  = sbox[gt];
    float mcx = (m.x + m.z) * 0.5f, mcy = (m.y + m.w) * 0.5f;
    float mw  = m.z - m.x,          mh  = m.w - m.y;
    float l0  = (mcx - an.x) / (0.1f * an.z);
    float l1  = (mcy - an.y) / (0.1f * an.w);
    float l2  = logf(mw / an.z) / 0.2f;
    float l3  = logf(mh / an.w) / 0.2f;

    size_t base = ((size_t)b * Av + a) * 4;
    out[base + 0] = l0; out[base + 1] = l1;
    out[base + 2] = l2; out[base + 3] = l3;
    out[(size_t)Bv * Av * 4 + (size_t)b * Av + a] = (float)conf;
}

extern "C" void kernel_launch(void* const* d_in, const int* in_sizes, int n_in,
                              void* d_out, int out_size) {
    const float* targets = (const float*)d_in[0];   // (B, T, 5) f32
    const float* anchors = (const float*)d_in[1];   // (A, 4)   f32
    float* out = (float*)d_out;                     // loc (B*A*4) then conf (B*A)

    k_fill<<<(Bv * Tv + 255) / 256, 256>>>();

    dim3 g((Av + 255) / 256, Bv);
    k_fused<<<g, 256>>>(targets, anchors);
    k_epi  <<<g, 256>>>(targets, anchors, out);
}

// round 4
// speedup vs baseline: 1.7605x; 1.7605x over previous
#include <cuda_runtime.h>
#include <cuda_bf16.h>

#define Bv 64
#define Tv 100
#define Av 8732
typedef unsigned long long ull;

// per-(b,t) packed winner: (q_bits << 32) | (0xFFFFFFFF - anchor)
__device__ ull   g_key[Bv * Tv];
// per-(b,t) prepass filter slope, pre-multiplied by 4 (for folded compare)
__device__ float g_slope4[Bv * Tv];
// per-(b,a) best-over-t: {q_bits, ct}
__device__ int2  g_best[Bv * Av];

// safe reject-filter slope for quotient q: never rejects q' >= q
__device__ __forceinline__ float slope_of(float q) {
    return __fmul_rn(__fdividef(q, __fadd_rn(1.f, q)), 0.99999f);
}

// K0 (prepass): per (b,t) approximate max IoU over a 1/64 anchor subset ->
// safe per-t filter slope. Also zeroes g_key. Grid: (Bv), block 128.
__global__ __launch_bounds__(128) void k_pre(
        const float* __restrict__ targets,
        const float* __restrict__ anchors) {
    const int b = blockIdx.x, t = threadIdx.x;
    if (t >= Tv) return;
    g_key[b * Tv + t] = 0ull;

    const float* tp = targets + ((size_t)b * Tv + t) * 5;
    float x1 = tp[0], y1 = tp[1], x2 = tp[2], y2 = tp[3];
    float area = __fmul_rn(__fsub_rn(x2, x1), __fsub_rn(y2, y1));

    float qmax = 0.f;
    for (int a = (t * 37) & 63; a < Av; a += 64) {
        float4 an = __ldg((const float4*)anchors + a);
        float hw = an.z * 0.5f, hh = an.w * 0.5f;
        float dx = fminf(x2, an.x + hw) - fmaxf(x1, an.x - hw);
        float dy = fminf(y2, an.y + hh) - fmaxf(y1, an.y - hh);
        if (dx > 0.f && dy > 0.f) {
            float inter = dx * dy;
            float q = __fdividef(inter, area + an.z * an.w - inter);
            qmax = fmaxf(qmax, q);
        }
    }
    // lower-bound with generous margin (covers __fdividef error), then slope*4
    float qlb = qmax * 0.999f;
    float s4  = (qlb > 0.f) ? __fmul_rn(slope_of(qlb), 4.f) : 0.f;
    g_slope4[b * Tv + t] = s4;
}

// K1 (fused): one pass over all (b,t,a) IoUs, both argmax reductions.
// Grid: (ceil(A/256), B), block 256. Thread = one anchor; loop over t.
__global__ __launch_bounds__(256) void k_fused(
        const float* __restrict__ targets,
        const float* __restrict__ anchors) {
    __shared__ float4 sbox[Tv];
    __shared__ float2 saux[Tv];   // x = area, y = slp4 (fixed per t)
    __shared__ ull    skey[Tv];

    const int b   = blockIdx.y;
    const int tid = threadIdx.x;
    if (tid < Tv) {
        const float* tp = targets + ((size_t)b * Tv + tid) * 5;
        float x1 = tp[0], y1 = tp[1], x2 = tp[2], y2 = tp[3];
        sbox[tid] = make_float4(x1, y1, x2, y2);
        saux[tid] = make_float2(__fmul_rn(__fsub_rn(x2, x1), __fsub_rn(y2, y1)),
                                g_slope4[b * Tv + tid]);
        skey[tid] = 0ull;
    }
    __syncthreads();

    const int a0 = blockIdx.x * 256 + tid;
    const int a  = min(a0, Av - 1);          // clamped lanes duplicate a=Av-1 (harmless)

    float4 an = __ldg((const float4*)anchors + a);
    float hw  = __fmul_rn(an.z, 0.5f), hh = __fmul_rn(an.w, 0.5f);
    float ax1 = __fsub_rn(an.x, hw),  ay1 = __fsub_rn(an.y, hh);
    float ax2 = __fadd_rn(an.x, hw),  ay2 = __fadd_rn(an.y, hh);
    float aa  = __fmul_rn(__fsub_rn(ax2, ax1), __fsub_rn(ay2, ay1));

    float q = 0.f, s4 = 0.f; int ct = 0;
#pragma unroll 5
    for (int t = 0; t < Tv; t++) {
        float4 bx = sbox[t];
        float2 ax = saux[t];
        // pr = 4*inter exactly; 0.5-scales folded out (pow2 scaling is exact)
        float ux = __fsub_rn(fminf(bx.z, ax2), fmaxf(bx.x, ax1));
        float uy = __fsub_rn(fminf(bx.w, ay2), fmaxf(bx.y, ay1));
        float px = __fadd_rn(ux, fabsf(ux));
        float py = __fadd_rn(uy, fabsf(uy));
        float pr = __fmul_rn(px, py);
        float sab = __fadd_rn(ax.x, aa);
        float m4  = fminf(s4, ax.y);
        if (pr > __fmul_rn(m4, sab)) {                        // rare path
            float inter = __fmul_rn(pr, 0.25f);               // exact
            float qc = __fdiv_rn(inter, __fsub_rn(sab, inter));   // exact IoU
            if (qc > q) {                                     // first-t wins
                q = qc; ct = t; s4 = __fmul_rn(slope_of(qc), 4.f);
            }
            if (pr > __fmul_rn(ax.y, sab)) {                  // per-t candidate
                ull key = ((ull)__float_as_uint(qc) << 32)
                        | (unsigned)(0xFFFFFFFFu - (unsigned)a);
                atomicMax(&skey[t], key);                     // tie -> lowest a
            }
        }
    }

    if (a0 < Av)
        g_best[(size_t)b * Av + a0] = make_int2(__float_as_int(q), ct);

    __syncthreads();
    if (tid < Tv && skey[tid])
        atomicMax(&g_key[b * Tv + tid], skey[tid]);
}

// K2 (epilogue): per (b,a) resolve forced match, encode loc, compute conf.
__global__ __launch_bounds__(256) void k_epi(
        const float* __restrict__ targets,
        const float* __restrict__ anchors,
        float* __restrict__ out) {
    __shared__ float4 sbox[Tv];
    __shared__ float  slab[Tv];
    __shared__ int    sforced[256];

    const int b   = blockIdx.y;
    const int tid = threadIdx.x;
    const unsigned a0blk = blockIdx.x * 256u;

    sforced[tid] = -1;
    if (tid < Tv) {
        const float* tp = targets + ((size_t)b * Tv + tid) * 5;
        sbox[tid] = make_float4(tp[0], tp[1], tp[2], tp[3]);
        slab[tid] = tp[4];
    }
    __syncthreads();
    if (tid < Tv) {
        ull key = g_key[b * Tv + tid];
        unsigned aw = key ? (0xFFFFFFFFu - (unsigned)key) : 0u;
        unsigned rel = aw - a0blk;
        if (rel < 256u) atomicMax(&sforced[rel], tid);   // max t = last write wins
    }
    __syncthreads();

    const unsigned a = a0blk + tid;
    if (a >= Av) return;

    float4 an = __ldg((const float4*)anchors + a);
    int2 bv  = g_best[(size_t)b * Av + a];
    float q  = __int_as_float(bv.x);
    int   ct = bv.y;
    int forced = sforced[tid];

    int gt, conf;
    if (forced >= 0) { gt = forced; conf = (int)slab[gt] + 1; }   // overlap := 1.0
    else             { gt = ct;     conf = (q < 0.5f) ? 0 : ((int)slab[gt] + 1); }

    float4 m  = sbox[gt];
    float mcx = (m.x + m.z) * 0.5f, mcy = (m.y + m.w) * 0.5f;
    float mw  = m.z - m.x,          mh  = m.w - m.y;
    float l0  = (mcx - an.x) / (0.1f * an.z);
    float l1  = (mcy - an.y) / (0.1f * an.w);
    float l2  = logf(mw / an.z) / 0.2f;
    float l3  = logf(mh / an.w) / 0.2f;

    size_t base = ((size_t)b * Av + a) * 4;
    out[base + 0] = l0; out[base + 1] = l1;
    out[base + 2] = l2; out[base + 3] = l3;
    out[(size_t)Bv * Av * 4 + (size_t)b * Av + a] = (float)conf;
}

extern "C" void kernel_launch(void* const* d_in, const int* in_sizes, int n_in,
                              void* d_out, int out_size) {
    const float* targets = (const float*)d_in[0];   // (B, T, 5) f32
    const float* anchors = (const float*)d_in[1];   // (A, 4)   f32
    float* out = (float*)d_out;                     // loc (B*A*4) then conf (B*A)

    k_pre<<<Bv, 128>>>(targets, anchors);

    dim3 g((Av + 255) / 256, Bv);
    k_fused<<<g, 256>>>(targets, anchors);
    k_epi  <<<g, 256>>>(targets, anchors, out);
}